// round 9
// baseline (speedup 1.0000x reference)
#include <cuda_runtime.h>
#include <stdint.h>

// out[i] = -cost[i, inputs[i]] * mask[i]
// cost: float32 [N, V], inputs: int32 [N], mask: float32 [N], out: float32 [N]
// N = 16384, V = 32000.
//
// Resubmission of R8 (bench died at device-acquire: "device busy" — transient
// infra, kernel never ran). Guard-free x2 variant: N/2 threads, each handles
// rows 2t and 2t+1.
//  - int2/float2 loads and float2 store: half the coalesced transactions
//  - half the warps of the scalar version (256 vs 512) -> less ramp/issue
//  - 2 independent L2-hot gathers per thread
//  - no bounds check (N multiple of 256 guaranteed by dispatch); guarded
//    scalar kernel retained as generic fallback.

__global__ void __launch_bounds__(128, 1)
masked_nll_x2(const float* __restrict__ cost,
              const int2* __restrict__ idx2,
              const float2* __restrict__ mask2,
              float2* __restrict__ out2,
              unsigned v) {
    unsigned t = blockIdx.x * 128u + threadIdx.x;
    int2   idx = idx2[t];
    float2 m   = mask2[t];

    unsigned base = 2u * t * v;          // max 16384*32000 < 2^31, exact
    float p0 = __ldg(cost + (base     + (unsigned)idx.x));
    float p1 = __ldg(cost + (base + v + (unsigned)idx.y));

    float2 r;
    r.x = -p0 * m.x;
    r.y = -p1 * m.y;
    out2[t] = r;
}

__global__ void __launch_bounds__(128, 1)
masked_nll_guarded(const float* __restrict__ cost,
                   const int* __restrict__ idx,
                   const float* __restrict__ mask,
                   float* __restrict__ out,
                   int n, unsigned v) {
    unsigned i = blockIdx.x * 128u + threadIdx.x;
    if (i >= (unsigned)n) return;
    unsigned off = i * v + (unsigned)idx[i];
    out[i] = -__ldg(cost + off) * mask[i];
}

extern "C" void kernel_launch(void* const* d_in, const int* in_sizes, int n_in,
                              void* d_out, int out_size) {
    const float* cost = (const float*)d_in[0];
    const int*   idx  = (const int*)d_in[1];
    const float* mask = (const float*)d_in[2];
    float*       out  = (float*)d_out;

    int n = in_sizes[1];                      // N = element count of inputs[]
    unsigned v = (unsigned)(in_sizes[0] / n); // V = cost elems / N

    if (n % 256 == 0) {
        // n/2 threads, 128 per CTA
        masked_nll_x2<<<n / 256, 128>>>(cost, (const int2*)idx,
                                        (const float2*)mask, (float2*)out, v);
    } else {
        masked_nll_guarded<<<(n + 127) / 128, 128>>>(cost, idx, mask, out, n, v);
    }
}

// round 10
// speedup vs baseline: 1.0385x; 1.0385x over previous
#include <cuda_runtime.h>
#include <stdint.h>

// out[i] = -cost[i, inputs[i]] * mask[i]
// cost: float32 [N, V], inputs: int32 [N], mask: float32 [N], out: float32 [N]
// N = 16384, V = 32000.
//
// Exact revert to the best measured configuration (R7, 4.70us):
//   scalar, guard-free, 128 threads x 128 CTAs.
// Measured comparison set:
//   scalar+guard 6.53 | x2+guard 6.62 | x2 no-guard (64 CTAs) 6.91 | THIS 4.70
// Working theory: with per-node graph replay, wall time ~ slowest SM. 128 CTAs
// spreads the 16384 scattered gathers across ~128 SMs' L1tex queues (128/SM),
// and the scalar form has the shortest per-thread dependency chain
// (idx LDG -> gather LDG, one address computation). Vector variants halve the
// CTA count and add register unpack + second dependent address chain per
// thread, which costs more than the saved coalesced transactions (DRAM ~3%).

__global__ void __launch_bounds__(128, 1)
masked_nll_exact(const float* __restrict__ cost,
                 const int* __restrict__ idx,
                 const float* __restrict__ mask,
                 float* __restrict__ out,
                 unsigned v) {
    unsigned i = blockIdx.x * 128u + threadIdx.x;
    // Element offset fits in 32 bits: 16384*32000 + 31999 < 2^31.
    unsigned off = i * v + (unsigned)idx[i];
    out[i] = -__ldg(cost + off) * mask[i];
}

__global__ void __launch_bounds__(128, 1)
masked_nll_guarded(const float* __restrict__ cost,
                   const int* __restrict__ idx,
                   const float* __restrict__ mask,
                   float* __restrict__ out,
                   int n, unsigned v) {
    unsigned i = blockIdx.x * 128u + threadIdx.x;
    if (i >= (unsigned)n) return;
    unsigned off = i * v + (unsigned)idx[i];
    out[i] = -__ldg(cost + off) * mask[i];
}

extern "C" void kernel_launch(void* const* d_in, const int* in_sizes, int n_in,
                              void* d_out, int out_size) {
    const float* cost = (const float*)d_in[0];
    const int*   idx  = (const int*)d_in[1];
    const float* mask = (const float*)d_in[2];
    float*       out  = (float*)d_out;

    int n = in_sizes[1];                      // N = element count of inputs[]
    unsigned v = (unsigned)(in_sizes[0] / n); // V = cost elems / N

    const int threads = 128;
    if (n % threads == 0) {
        masked_nll_exact<<<n / threads, threads>>>(cost, idx, mask, out, v);
    } else {
        masked_nll_guarded<<<(n + threads - 1) / threads, threads>>>(
            cost, idx, mask, out, n, v);
    }
}

// round 11
// speedup vs baseline: 1.4694x; 1.4150x over previous
#include <cuda_runtime.h>
#include <stdint.h>

// out[i] = -cost[i, inputs[i]] * mask[i]
// cost: float32 [N, V], inputs: int32 [N], mask: float32 [N], out: float32 [N]
// N = 16384, V = 32000.
//
// CONVERGED. Final configuration: scalar, guard-free, 128 threads x 128 CTAs.
//
// Session-noise evidence: this byte-identical kernel measured 4.70us (R7) and
// 6.66us (R10); structurally different variants (scalar/x2/x4, guarded or not,
// 64/128 CTAs) all fall in 6.5-6.9us. => inter-session variance ~±2us, all
// configs statistically tied. ncu is invariant across variants (DRAM ~3%,
// issue ~0.7%): the kernel body is ~1-1.5us (two dependent L2-hot loads + one
// FMA per element); the rest is graph-replay/launch overhead outside kernel
// control. No remaining optimization has a predicted effect above the noise.

__global__ void __launch_bounds__(128, 1)
masked_nll_exact(const float* __restrict__ cost,
                 const int* __restrict__ idx,
                 const float* __restrict__ mask,
                 float* __restrict__ out,
                 unsigned v) {
    unsigned i = blockIdx.x * 128u + threadIdx.x;
    // Element offset fits in 32 bits: 16384*32000 + 31999 < 2^31.
    unsigned off = i * v + (unsigned)idx[i];
    out[i] = -__ldg(cost + off) * mask[i];
}

__global__ void __launch_bounds__(128, 1)
masked_nll_guarded(const float* __restrict__ cost,
                   const int* __restrict__ idx,
                   const float* __restrict__ mask,
                   float* __restrict__ out,
                   int n, unsigned v) {
    unsigned i = blockIdx.x * 128u + threadIdx.x;
    if (i >= (unsigned)n) return;
    unsigned off = i * v + (unsigned)idx[i];
    out[i] = -__ldg(cost + off) * mask[i];
}

extern "C" void kernel_launch(void* const* d_in, const int* in_sizes, int n_in,
                              void* d_out, int out_size) {
    const float* cost = (const float*)d_in[0];
    const int*   idx  = (const int*)d_in[1];
    const float* mask = (const float*)d_in[2];
    float*       out  = (float*)d_out;

    int n = in_sizes[1];                      // N = element count of inputs[]
    unsigned v = (unsigned)(in_sizes[0] / n); // V = cost elems / N

    const int threads = 128;
    if (n % threads == 0) {
        masked_nll_exact<<<n / threads, threads>>>(cost, idx, mask, out, v);
    } else {
        masked_nll_guarded<<<(n + threads - 1) / threads, threads>>>(
            cost, idx, mask, out, n, v);
    }
}